// round 9
// baseline (speedup 1.0000x reference)
#include <cuda_runtime.h>
#include <cuda_bf16.h>
#include <mma.h>
#include <math.h>
#include <stdint.h>

using namespace nvcuda;

// Problem constants
#define NN 20000
#define NPAD 20224            // 79 * 256 padded M (padding rows never consumed)
#define EE 640000
#define GG 128
#define RR 8
#define KSPLIT 384            // [hi | hi | lo] split-K
#define NOUT1 1152
#define NOUT2 512

// ---------------- scratch (device globals; device-code use only) -----------
__device__ float g_y[(size_t)NPAD * 1024];               // ~83 MB (relations)
__device__ float g_hroot[(size_t)NPAD * GG];             // x @ root
__device__ float g_hacc[NN * GG];
__device__ __nv_bfloat16 g_split[(size_t)NPAD * KSPLIT]; // A' (x, later h)
__device__ __nv_bfloat16 g_b1[(size_t)NOUT1 * KSPLIT];
__device__ __nv_bfloat16 g_b2[(size_t)NOUT2 * KSPLIT];
__device__ float g_q[(size_t)NPAD * GG];
__device__ float g_k[(size_t)NPAD * GG];
__device__ float g_v[(size_t)NPAD * GG];
__device__ float g_s[(size_t)NPAD * GG];
__device__ float g_cnt[NN * RR];
__device__ float g_e[EE];
__device__ float g_den[NN];

// ---------------- vector reduction (sm_90+ PTX, arch-generic) ---------------
__device__ __forceinline__ void red_add_v4(float* p, float a, float b,
                                           float c, float d) {
    asm volatile("red.global.add.v4.f32 [%0], {%1, %2, %3, %4};"
                 :: "l"(p), "f"(a), "f"(b), "f"(c), "f"(d) : "memory");
}

// ---------------- zero / count ----------------------------------------------
__global__ void zero_kernel(float* __restrict__ out) {
    int i = blockIdx.x * blockDim.x + threadIdx.x;
    if (i < NN * GG / 4) {
        *(float4*)&g_hacc[i * 4] = make_float4(0.f, 0.f, 0.f, 0.f);
        *(float4*)&out[i * 4]    = make_float4(0.f, 0.f, 0.f, 0.f);
    }
    if (i < NN * RR) g_cnt[i] = 0.f;
    if (i < NN) g_den[i] = 0.f;
}

__global__ void count_kernel(const int* __restrict__ dst,
                             const int* __restrict__ etype) {
    int e = blockIdx.x * blockDim.x + threadIdx.x;
    if (e >= EE) return;
    atomicAdd(&g_cnt[dst[e] * RR + etype[e]], 1.0f);
}

// ---------------- split packing ---------------------------------------------
__device__ __forceinline__ void split_write(__nv_bfloat16* row, int k, float v) {
    __nv_bfloat16 hi = __float2bfloat16(v);
    __nv_bfloat16 lo = __float2bfloat16(v - __bfloat162float(hi));
    row[k] = hi; row[GG + k] = hi; row[2 * GG + k] = lo;   // A-style [hi|hi|lo]
}
__device__ __forceinline__ void split_write_b(__nv_bfloat16* row, int k, float v) {
    __nv_bfloat16 hi = __float2bfloat16(v);
    __nv_bfloat16 lo = __float2bfloat16(v - __bfloat162float(hi));
    row[k] = hi; row[GG + k] = lo; row[2 * GG + k] = hi;   // B-style [hi|lo|hi]
}

__global__ void pack_b1_kernel(const float* __restrict__ rgcn_w,
                               const float* __restrict__ root) {
    int i = blockIdx.x * blockDim.x + threadIdx.x;
    if (i >= NOUT1 * GG) return;
    int np = i >> 7, k = i & 127;
    float v;
    if (np < 1024) {
        int r = np >> 7, n = np & 127;
        v = rgcn_w[r * 16384 + k * 128 + n];
    } else {
        v = root[k * 128 + (np - 1024)];
    }
    split_write_b(&g_b1[(size_t)np * KSPLIT], k, v);
}

__global__ void pack_b2_kernel(const float* __restrict__ Wq,
                               const float* __restrict__ Wk,
                               const float* __restrict__ Wv,
                               const float* __restrict__ Ws) {
    int i = blockIdx.x * blockDim.x + threadIdx.x;
    if (i >= NOUT2 * GG) return;
    int np = i >> 7, k = i & 127;
    int sel = np >> 7, n = np & 127;
    const float* W = (sel == 0) ? Wq : (sel == 1) ? Wk : (sel == 2) ? Wv : Ws;
    split_write_b(&g_b2[(size_t)np * KSPLIT], k, W[k * 128 + n]);
}

__global__ void split_x_kernel(const float* __restrict__ x) {
    int i = blockIdx.x * blockDim.x + threadIdx.x;
    if (i >= NN * GG) return;
    int m = i >> 7, k = i & 127;
    split_write(&g_split[(size_t)m * KSPLIT], k, x[i]);
}

// ---------------- WMMA bf16 GEMM: 256x128 CTA tile, warp tile 64x64 ---------
// 8 warps as 4x2; acc 4x4 of 16x16. BK=32. M padded, no bounds checks.
__global__ void __launch_bounds__(256, 1)
gemm_wmma_kernel(int mode) {
    __shared__ __nv_bfloat16 As[256][40];
    __shared__ __nv_bfloat16 Bs[128][40];
    int tid = threadIdx.x;
    int warp = tid >> 5;
    int wm = warp >> 1, wn = warp & 1;
    int row0 = blockIdx.x * 256;
    int n0 = blockIdx.y * 128;
    const __nv_bfloat16* Bgm = (mode == 0) ? g_b1 : g_b2;

    wmma::fragment<wmma::accumulator, 16, 16, 16, float> acc[4][4];
    #pragma unroll
    for (int i = 0; i < 4; i++)
        #pragma unroll
        for (int j = 0; j < 4; j++) wmma::fill_fragment(acc[i][j], 0.f);

    for (int k0 = 0; k0 < KSPLIT; k0 += 32) {
        // A tile: 256x32 bf16 = 1024 uint4, 4 per thread
        #pragma unroll
        for (int i = 0; i < 4; i++) {
            int idx = tid + i * 256;
            int r = idx >> 2;
            int kc = (idx & 3) * 8;
            *(uint4*)&As[r][kc] =
                *(const uint4*)&g_split[(size_t)(row0 + r) * KSPLIT + k0 + kc];
        }
        // B tile: 128x32 bf16 = 512 uint4, 2 per thread
        #pragma unroll
        for (int i = 0; i < 2; i++) {
            int idx = tid + i * 256;
            int r = idx >> 2;
            int kc = (idx & 3) * 8;
            *(uint4*)&Bs[r][kc] =
                *(const uint4*)&Bgm[(size_t)(n0 + r) * KSPLIT + k0 + kc];
        }
        __syncthreads();
        #pragma unroll
        for (int ks = 0; ks < 32; ks += 16) {
            wmma::fragment<wmma::matrix_a, 16, 16, 16, __nv_bfloat16, wmma::row_major> af[4];
            wmma::fragment<wmma::matrix_b, 16, 16, 16, __nv_bfloat16, wmma::col_major> bf[4];
            #pragma unroll
            for (int i = 0; i < 4; i++)
                wmma::load_matrix_sync(af[i], &As[wm * 64 + i * 16][ks], 40);
            #pragma unroll
            for (int j = 0; j < 4; j++)
                wmma::load_matrix_sync(bf[j], &Bs[wn * 64 + j * 16][ks], 40);
            #pragma unroll
            for (int i = 0; i < 4; i++)
                #pragma unroll
                for (int j = 0; j < 4; j++)
                    wmma::mma_sync(acc[i][j], af[i], bf[j], acc[i][j]);
        }
        __syncthreads();
    }

    if (mode == 0) {
        if (blockIdx.y < 8) {
            #pragma unroll
            for (int i = 0; i < 4; i++)
                #pragma unroll
                for (int j = 0; j < 4; j++)
                    wmma::store_matrix_sync(
                        &g_y[(size_t)(row0 + wm * 64 + i * 16) * 1024
                             + n0 + wn * 64 + j * 16],
                        acc[i][j], 1024, wmma::mem_row_major);
        } else {
            #pragma unroll
            for (int i = 0; i < 4; i++)
                #pragma unroll
                for (int j = 0; j < 4; j++)
                    wmma::store_matrix_sync(
                        &g_hroot[(size_t)(row0 + wm * 64 + i * 16) * GG
                                 + wn * 64 + j * 16],
                        acc[i][j], GG, wmma::mem_row_major);
        }
    } else {
        int seg = blockIdx.y;
        float* Cb = (seg == 0) ? g_q : (seg == 1) ? g_k : (seg == 2) ? g_v : g_s;
        #pragma unroll
        for (int i = 0; i < 4; i++)
            #pragma unroll
            for (int j = 0; j < 4; j++)
                wmma::store_matrix_sync(
                    &Cb[(size_t)(row0 + wm * 64 + i * 16) * GG + wn * 64 + j * 16],
                    acc[i][j], GG, wmma::mem_row_major);
    }
}

// ---------------- scatter: hacc[dst] += y[src, et*128..]/cnt ----------------
__global__ void scatter_y_kernel(const int* __restrict__ src,
                                 const int* __restrict__ dst,
                                 const int* __restrict__ etype) {
    int e = blockIdx.x * 8 + (threadIdx.x >> 5);
    if (e >= EE) return;
    int lane = threadIdx.x & 31;
    int s = src[e], d = dst[e], r = etype[e];
    float inv = 1.0f / fmaxf(g_cnt[d * RR + r], 1.0f);
    float4 yv = *(const float4*)&g_y[(size_t)s * 1024 + r * 128 + lane * 4];
    red_add_v4(&g_hacc[d * GG + lane * 4],
               yv.x * inv, yv.y * inv, yv.z * inv, yv.w * inv);
}

// h = relu(hacc + hroot + bias); write split(h) into g_split for GEMM2
__global__ void finalize_split_kernel(const float* __restrict__ bias) {
    int i = blockIdx.x * blockDim.x + threadIdx.x;
    if (i >= NN * GG) return;
    int m = i >> 7, c = i & 127;
    float h = g_hacc[i] + g_hroot[(size_t)m * GG + c] + bias[c];
    h = fmaxf(h, 0.f);
    split_write(&g_split[(size_t)m * KSPLIT], c, h);
}

// ---------------- attention (biases folded in here) -------------------------
__global__ void score_exp_kernel(const int* __restrict__ src,
                                 const int* __restrict__ dst,
                                 const float* __restrict__ bq,
                                 const float* __restrict__ bk) {
    int e = blockIdx.x * 8 + (threadIdx.x >> 5);
    if (e >= EE) return;
    int lane = threadIdx.x & 31;
    int s = src[e], d = dst[e];
    float4 bqv = *(const float4*)&bq[lane * 4];
    float4 bkv = *(const float4*)&bk[lane * 4];
    float4 qv = *(const float4*)&g_q[(size_t)d * GG + lane * 4];
    float4 kv = *(const float4*)&g_k[(size_t)s * GG + lane * 4];
    float acc = (qv.x + bqv.x) * (kv.x + bkv.x)
              + (qv.y + bqv.y) * (kv.y + bkv.y)
              + (qv.z + bqv.z) * (kv.z + bkv.z)
              + (qv.w + bqv.w) * (kv.w + bkv.w);
    #pragma unroll
    for (int o = 16; o; o >>= 1) acc += __shfl_xor_sync(0xFFFFFFFFu, acc, o);
    if (lane == 0) {
        float ex = __expf(acc * 0.08838834764831845f);  // 1/sqrt(128)
        g_e[e] = ex;
        atomicAdd(&g_den[d], ex);
    }
}

__global__ void scatter_v_kernel(const int* __restrict__ src,
                                 const int* __restrict__ dst,
                                 const float* __restrict__ bv,
                                 float* __restrict__ out) {
    int e = blockIdx.x * 8 + (threadIdx.x >> 5);
    if (e >= EE) return;
    int lane = threadIdx.x & 31;
    int s = src[e], d = dst[e];
    float alpha = g_e[e] / fmaxf(g_den[d], 1e-16f);
    float4 bvv = *(const float4*)&bv[lane * 4];
    float4 vv = *(const float4*)&g_v[(size_t)s * GG + lane * 4];
    red_add_v4(out + (size_t)d * GG + lane * 4,
               alpha * (vv.x + bvv.x), alpha * (vv.y + bvv.y),
               alpha * (vv.z + bvv.z), alpha * (vv.w + bvv.w));
}

// out = relu(attn_acc + skip + bs)
__global__ void final_kernel(float* __restrict__ out,
                             const float* __restrict__ bs) {
    int i = blockIdx.x * blockDim.x + threadIdx.x;
    if (i >= NN * GG) return;
    int m = i >> 7, c = i & 127;
    out[i] = fmaxf(out[i] + g_s[(size_t)m * GG + c] + bs[c], 0.f);
}

// ---------------------------------------------------------------------------
extern "C" void kernel_launch(void* const* d_in, const int* in_sizes, int n_in,
                              void* d_out, int out_size) {
    const float* x        = (const float*)d_in[0];
    const int* edge_index = (const int*)d_in[1];   // [2, E]: src then dst
    const int* etype      = (const int*)d_in[2];
    const float* rgcn_w   = (const float*)d_in[3];
    const float* rgcn_root= (const float*)d_in[4];
    const float* rgcn_b   = (const float*)d_in[5];
    const float* Wq = (const float*)d_in[6];  const float* bq = (const float*)d_in[7];
    const float* Wk = (const float*)d_in[8];  const float* bk = (const float*)d_in[9];
    const float* Wv = (const float*)d_in[10]; const float* bv = (const float*)d_in[11];
    const float* Ws = (const float*)d_in[12]; const float* bs = (const float*)d_in[13];
    float* out = (float*)d_out;

    const int* src = edge_index;
    const int* dst = edge_index + EE;

    // 0-2: packs + split
    pack_b1_kernel<<<(NOUT1 * GG + 255) / 256, 256>>>(rgcn_w, rgcn_root);
    pack_b2_kernel<<<(NOUT2 * GG + 255) / 256, 256>>>(Wq, Wk, Wv, Ws);
    split_x_kernel<<<(NN * GG + 255) / 256, 256>>>(x);
    // 3 (ncu capture slot): y = x @ [W_r | root]
    {
        dim3 g(NPAD / 256, 9);
        gemm_wmma_kernel<<<g, 256>>>(0);
    }
    // 4: zero hacc/out/cnt/den
    zero_kernel<<<(NN * GG / 4 + 255) / 256, 256>>>(out);
    // 5: per-(dst,rel) counts
    count_kernel<<<(EE + 255) / 256, 256>>>(dst, etype);
    // 6: aggregate transformed features (vector reds)
    scatter_y_kernel<<<(EE + 7) / 8, 256>>>(src, dst, etype);
    // 7: h = relu(hacc + hroot + bias), split into g_split
    finalize_split_kernel<<<(NN * GG + 255) / 256, 256>>>(rgcn_b);
    // 8: q,k,v,skip = h @ [Wq|Wk|Wv|Ws]
    {
        dim3 g(NPAD / 256, 4);
        gemm_wmma_kernel<<<g, 256>>>(1);
    }
    // 9: fused score+exp+den (bq/bk folded in)
    score_exp_kernel<<<(EE + 7) / 8, 256>>>(src, dst, bq, bk);
    // 10: alpha*(v+bv) scatter into out (vector reds)
    scatter_v_kernel<<<(EE + 7) / 8, 256>>>(src, dst, bv, out);
    // 11: out = relu(out + skip + bs)
    final_kernel<<<(NN * GG + 255) / 256, 256>>>(out, bs);
}

// round 10
// speedup vs baseline: 1.2014x; 1.2014x over previous
#include <cuda_runtime.h>
#include <cuda_bf16.h>
#include <mma.h>
#include <math.h>
#include <stdint.h>

using namespace nvcuda;

// Problem constants
#define NN 20000
#define NPAD 20096            // 157 * 128 padded M (padding rows never consumed)
#define EE 640000
#define GG 128
#define RR 8
#define KSPLIT 384            // [hi | hi | lo] split-K
#define NOUT1 1152
#define NOUT2 512

// ---------------- scratch (device globals; device-code use only) -----------
__device__ float g_y[(size_t)NPAD * 1024];               // ~82 MB (relations)
__device__ float g_hroot[(size_t)NPAD * GG];             // x @ root
__device__ float g_hacc[NN * GG];
__device__ __nv_bfloat16 g_split[(size_t)NPAD * KSPLIT]; // A' (x, later h)
__device__ __nv_bfloat16 g_b1[(size_t)NOUT1 * KSPLIT];
__device__ __nv_bfloat16 g_b2[(size_t)NOUT2 * KSPLIT];
__device__ float g_q[(size_t)NPAD * GG];
__device__ float g_k[(size_t)NPAD * GG];
__device__ float g_v[(size_t)NPAD * GG];
__device__ float g_s[(size_t)NPAD * GG];
__device__ float g_cnt[NN * RR];
__device__ float g_den[NN];

// ---------------- vector reduction (sm_90+ PTX, arch-generic) ---------------
__device__ __forceinline__ void red_add_v4(float* p, float a, float b,
                                           float c, float d) {
    asm volatile("red.global.add.v4.f32 [%0], {%1, %2, %3, %4};"
                 :: "l"(p), "f"(a), "f"(b), "f"(c), "f"(d) : "memory");
}

// ---------------- zero / count ----------------------------------------------
__global__ void zero_kernel(float* __restrict__ out) {
    int i = blockIdx.x * blockDim.x + threadIdx.x;
    if (i < NN * GG / 4) {
        *(float4*)&g_hacc[i * 4] = make_float4(0.f, 0.f, 0.f, 0.f);
        *(float4*)&out[i * 4]    = make_float4(0.f, 0.f, 0.f, 0.f);
    }
    if (i < NN * RR) g_cnt[i] = 0.f;
    if (i < NN) g_den[i] = 0.f;
}

__global__ void count_kernel(const int* __restrict__ dst,
                             const int* __restrict__ etype) {
    int e = blockIdx.x * blockDim.x + threadIdx.x;
    if (e >= EE) return;
    atomicAdd(&g_cnt[dst[e] * RR + etype[e]], 1.0f);
}

// ---------------- split packing ---------------------------------------------
__device__ __forceinline__ void split_write(__nv_bfloat16* row, int k, float v) {
    __nv_bfloat16 hi = __float2bfloat16(v);
    __nv_bfloat16 lo = __float2bfloat16(v - __bfloat162float(hi));
    row[k] = hi; row[GG + k] = hi; row[2 * GG + k] = lo;   // A-style [hi|hi|lo]
}
__device__ __forceinline__ void split_write_b(__nv_bfloat16* row, int k, float v) {
    __nv_bfloat16 hi = __float2bfloat16(v);
    __nv_bfloat16 lo = __float2bfloat16(v - __bfloat162float(hi));
    row[k] = hi; row[GG + k] = lo; row[2 * GG + k] = hi;   // B-style [hi|lo|hi]
}

__global__ void pack_b1_kernel(const float* __restrict__ rgcn_w,
                               const float* __restrict__ root) {
    int i = blockIdx.x * blockDim.x + threadIdx.x;
    if (i >= NOUT1 * GG) return;
    int np = i >> 7, k = i & 127;
    float v;
    if (np < 1024) {
        int r = np >> 7, n = np & 127;
        v = rgcn_w[r * 16384 + k * 128 + n];
    } else {
        v = root[k * 128 + (np - 1024)];
    }
    split_write_b(&g_b1[(size_t)np * KSPLIT], k, v);
}

__global__ void pack_b2_kernel(const float* __restrict__ Wq,
                               const float* __restrict__ Wk,
                               const float* __restrict__ Wv,
                               const float* __restrict__ Ws) {
    int i = blockIdx.x * blockDim.x + threadIdx.x;
    if (i >= NOUT2 * GG) return;
    int np = i >> 7, k = i & 127;
    int sel = np >> 7, n = np & 127;
    const float* W = (sel == 0) ? Wq : (sel == 1) ? Wk : (sel == 2) ? Wv : Ws;
    split_write_b(&g_b2[(size_t)np * KSPLIT], k, W[k * 128 + n]);
}

__global__ void split_x_kernel(const float* __restrict__ x) {
    int i = blockIdx.x * blockDim.x + threadIdx.x;
    if (i >= NN * GG) return;
    int m = i >> 7, k = i & 127;
    split_write(&g_split[(size_t)m * KSPLIT], k, x[i]);
}

// ---------------- WMMA bf16 GEMM: 128x128 block tile, BK=32 (R8 config) -----
// 8 warps as 4x2; each warp 32x64 (acc 2x4 of 16x16). M padded, no bounds checks.
__global__ void __launch_bounds__(256)
gemm_wmma_kernel(int mode) {
    __shared__ __nv_bfloat16 As[128][40];
    __shared__ __nv_bfloat16 Bs[128][40];
    int tid = threadIdx.x;
    int warp = tid >> 5;
    int wm = warp >> 1, wn = warp & 1;
    int row0 = blockIdx.x * 128;
    int n0 = blockIdx.y * 128;
    const __nv_bfloat16* Bgm = (mode == 0) ? g_b1 : g_b2;

    wmma::fragment<wmma::accumulator, 16, 16, 16, float> acc[2][4];
    #pragma unroll
    for (int i = 0; i < 2; i++)
        #pragma unroll
        for (int j = 0; j < 4; j++) wmma::fill_fragment(acc[i][j], 0.f);

    for (int k0 = 0; k0 < KSPLIT; k0 += 32) {
        #pragma unroll
        for (int i = 0; i < 2; i++) {
            int idx = tid + i * 256;
            int r = idx >> 2;
            int kc = (idx & 3) * 8;
            *(uint4*)&As[r][kc] =
                *(const uint4*)&g_split[(size_t)(row0 + r) * KSPLIT + k0 + kc];
            *(uint4*)&Bs[r][kc] =
                *(const uint4*)&Bgm[(size_t)(n0 + r) * KSPLIT + k0 + kc];
        }
        __syncthreads();
        #pragma unroll
        for (int ks = 0; ks < 32; ks += 16) {
            wmma::fragment<wmma::matrix_a, 16, 16, 16, __nv_bfloat16, wmma::row_major> af[2];
            wmma::fragment<wmma::matrix_b, 16, 16, 16, __nv_bfloat16, wmma::col_major> bf[4];
            #pragma unroll
            for (int i = 0; i < 2; i++)
                wmma::load_matrix_sync(af[i], &As[wm * 32 + i * 16][ks], 40);
            #pragma unroll
            for (int j = 0; j < 4; j++)
                wmma::load_matrix_sync(bf[j], &Bs[wn * 64 + j * 16][ks], 40);
            #pragma unroll
            for (int i = 0; i < 2; i++)
                #pragma unroll
                for (int j = 0; j < 4; j++)
                    wmma::mma_sync(acc[i][j], af[i], bf[j], acc[i][j]);
        }
        __syncthreads();
    }

    if (mode == 0) {
        if (blockIdx.y < 8) {
            #pragma unroll
            for (int i = 0; i < 2; i++)
                #pragma unroll
                for (int j = 0; j < 4; j++)
                    wmma::store_matrix_sync(
                        &g_y[(size_t)(row0 + wm * 32 + i * 16) * 1024
                             + n0 + wn * 64 + j * 16],
                        acc[i][j], 1024, wmma::mem_row_major);
        } else {
            #pragma unroll
            for (int i = 0; i < 2; i++)
                #pragma unroll
                for (int j = 0; j < 4; j++)
                    wmma::store_matrix_sync(
                        &g_hroot[(size_t)(row0 + wm * 32 + i * 16) * GG
                                 + wn * 64 + j * 16],
                        acc[i][j], GG, wmma::mem_row_major);
        }
    } else {
        int seg = blockIdx.y;
        float* Cb = (seg == 0) ? g_q : (seg == 1) ? g_k : (seg == 2) ? g_v : g_s;
        #pragma unroll
        for (int i = 0; i < 2; i++)
            #pragma unroll
            for (int j = 0; j < 4; j++)
                wmma::store_matrix_sync(
                    &Cb[(size_t)(row0 + wm * 32 + i * 16) * GG + wn * 64 + j * 16],
                    acc[i][j], GG, wmma::mem_row_major);
    }
}

// ---------------- scatter: hacc[dst] += y[src, et*128..]/cnt ----------------
__global__ void scatter_y_kernel(const int* __restrict__ src,
                                 const int* __restrict__ dst,
                                 const int* __restrict__ etype) {
    int e = blockIdx.x * 8 + (threadIdx.x >> 5);
    if (e >= EE) return;
    int lane = threadIdx.x & 31;
    int s = src[e], d = dst[e], r = etype[e];
    float inv = 1.0f / fmaxf(g_cnt[d * RR + r], 1.0f);
    float4 yv = *(const float4*)&g_y[(size_t)s * 1024 + r * 128 + lane * 4];
    red_add_v4(&g_hacc[d * GG + lane * 4],
               yv.x * inv, yv.y * inv, yv.z * inv, yv.w * inv);
}

// h = relu(hacc + hroot + bias); write split(h) into g_split for GEMM2
__global__ void finalize_split_kernel(const float* __restrict__ bias) {
    int i = blockIdx.x * blockDim.x + threadIdx.x;
    if (i >= NN * GG) return;
    int m = i >> 7, c = i & 127;
    float h = g_hacc[i] + g_hroot[(size_t)m * GG + c] + bias[c];
    h = fmaxf(h, 0.f);
    split_write(&g_split[(size_t)m * KSPLIT], c, h);
}

// ---------------- fused attention edge pass ---------------------------------
// e = exp(((q[d]+bq).(k[s]+bk))/sqrt(128));  den[d] += e;  out[d] += e*(v[s]+bv)
// Division by den deferred to final_kernel (mathematically identical).
__global__ void edge_attn_kernel(const int* __restrict__ src,
                                 const int* __restrict__ dst,
                                 const float* __restrict__ bq,
                                 const float* __restrict__ bk,
                                 const float* __restrict__ bv,
                                 float* __restrict__ out) {
    int e = blockIdx.x * 8 + (threadIdx.x >> 5);
    if (e >= EE) return;
    int lane = threadIdx.x & 31;
    int s = src[e], d = dst[e];
    float4 bqv = *(const float4*)&bq[lane * 4];
    float4 bkv = *(const float4*)&bk[lane * 4];
    float4 qv = *(const float4*)&g_q[(size_t)d * GG + lane * 4];
    float4 kv = *(const float4*)&g_k[(size_t)s * GG + lane * 4];
    float acc = (qv.x + bqv.x) * (kv.x + bkv.x)
              + (qv.y + bqv.y) * (kv.y + bkv.y)
              + (qv.z + bqv.z) * (kv.z + bkv.z)
              + (qv.w + bqv.w) * (kv.w + bkv.w);
    #pragma unroll
    for (int o = 16; o; o >>= 1) acc += __shfl_xor_sync(0xFFFFFFFFu, acc, o);
    // all lanes hold the full dot product after xor-reduction
    float ex = __expf(acc * 0.08838834764831845f);  // 1/sqrt(128)
    if (lane == 0) atomicAdd(&g_den[d], ex);
    float4 bvv = *(const float4*)&bv[lane * 4];
    float4 vv = *(const float4*)&g_v[(size_t)s * GG + lane * 4];
    red_add_v4(out + (size_t)d * GG + lane * 4,
               ex * (vv.x + bvv.x), ex * (vv.y + bvv.y),
               ex * (vv.z + bvv.z), ex * (vv.w + bvv.w));
}

// out = relu(attn_num/den + skip + bs)
__global__ void final_kernel(float* __restrict__ out,
                             const float* __restrict__ bs) {
    int i = blockIdx.x * blockDim.x + threadIdx.x;
    if (i >= NN * GG) return;
    int m = i >> 7, c = i & 127;
    float invden = 1.0f / fmaxf(g_den[m], 1e-16f);
    out[i] = fmaxf(out[i] * invden + g_s[(size_t)m * GG + c] + bs[c], 0.f);
}

// ---------------------------------------------------------------------------
extern "C" void kernel_launch(void* const* d_in, const int* in_sizes, int n_in,
                              void* d_out, int out_size) {
    const float* x        = (const float*)d_in[0];
    const int* edge_index = (const int*)d_in[1];   // [2, E]: src then dst
    const int* etype      = (const int*)d_in[2];
    const float* rgcn_w   = (const float*)d_in[3];
    const float* rgcn_root= (const float*)d_in[4];
    const float* rgcn_b   = (const float*)d_in[5];
    const float* Wq = (const float*)d_in[6];  const float* bq = (const float*)d_in[7];
    const float* Wk = (const float*)d_in[8];  const float* bk = (const float*)d_in[9];
    const float* Wv = (const float*)d_in[10]; const float* bv = (const float*)d_in[11];
    const float* Ws = (const float*)d_in[12]; const float* bs = (const float*)d_in[13];
    float* out = (float*)d_out;

    const int* src = edge_index;
    const int* dst = edge_index + EE;

    // 0-2: packs + split
    pack_b1_kernel<<<(NOUT1 * GG + 255) / 256, 256>>>(rgcn_w, rgcn_root);
    pack_b2_kernel<<<(NOUT2 * GG + 255) / 256, 256>>>(Wq, Wk, Wv, Ws);
    split_x_kernel<<<(NN * GG + 255) / 256, 256>>>(x);
    // 3 (ncu capture slot): y = x @ [W_r | root]
    {
        dim3 g(NPAD / 128, 9);
        gemm_wmma_kernel<<<g, 256>>>(0);
    }
    // 4: zero hacc/out/cnt/den
    zero_kernel<<<(NN * GG / 4 + 255) / 256, 256>>>(out);
    // 5: per-(dst,rel) counts
    count_kernel<<<(EE + 255) / 256, 256>>>(dst, etype);
    // 6: aggregate transformed features (vector reds)
    scatter_y_kernel<<<(EE + 7) / 8, 256>>>(src, dst, etype);
    // 7: h = relu(hacc + hroot + bias), split into g_split
    finalize_split_kernel<<<(NN * GG + 255) / 256, 256>>>(rgcn_b);
    // 8: q,k,v,skip = h @ [Wq|Wk|Wv|Ws]
    {
        dim3 g(NPAD / 128, 4);
        gemm_wmma_kernel<<<g, 256>>>(1);
    }
    // 9: fused attention edge pass (score+exp+den+weighted-V scatter)
    edge_attn_kernel<<<(EE + 7) / 8, 256>>>(src, dst, bq, bk, bv, out);
    // 10: out = relu(out/den + skip + bs)
    final_kernel<<<(NN * GG + 255) / 256, 256>>>(out, bs);
}